// round 4
// baseline (speedup 1.0000x reference)
#include <cuda_runtime.h>
#include <math.h>
#include <stdint.h>

// Problem constants
#define BB   4
#define TT   1024
#define CC   1024
#define HH   16
#define DD   64
#define FFD  4096
#define MR   (BB*TT)   // 4096 rows

// ---------------- scratch (allocation-free) ----------------
__device__ float g_h[(size_t)MR * CC];        // 16 MB  - LN output
__device__ float g_qkv[(size_t)MR * 3072];    // 48 MB  - qkv / (q + kv for cross)
__device__ float g_attn[(size_t)MR * CC];     // 16 MB  - merged attention out
__device__ float g_ff[(size_t)MR * FFD];      // 64 MB  - ff hidden

// ---------------- LayerNorm: one block per row, float4 I/O ----------------
__global__ __launch_bounds__(256)
void ln_kernel(const float* __restrict__ x, const float* __restrict__ w,
               const float* __restrict__ b, float* __restrict__ out)
{
    int row = blockIdx.x;
    int t = threadIdx.x;
    const float4* xr = (const float4*)(x + (size_t)row * CC);
    float4 v = xr[t];
    float s = v.x + v.y + v.z + v.w;
    __shared__ float red[8];
    __shared__ float red2[8];
    for (int off = 16; off; off >>= 1) s += __shfl_xor_sync(0xffffffffu, s, off);
    if ((t & 31) == 0) red[t >> 5] = s;
    __syncthreads();
    if (t < 8) {
        s = red[t];
        for (int off = 4; off; off >>= 1) s += __shfl_xor_sync(0xffu, s, off);
        if (t == 0) red[0] = s;
    }
    __syncthreads();
    float mu = red[0] * (1.f / CC);
    float dx = v.x - mu, dy = v.y - mu, dz = v.z - mu, dw = v.w - mu;
    float vv = dx*dx + dy*dy + dz*dz + dw*dw;
    for (int off = 16; off; off >>= 1) vv += __shfl_xor_sync(0xffffffffu, vv, off);
    if ((t & 31) == 0) red2[t >> 5] = vv;
    __syncthreads();
    if (t < 8) {
        vv = red2[t];
        for (int off = 4; off; off >>= 1) vv += __shfl_xor_sync(0xffu, vv, off);
        if (t == 0) red2[0] = vv;
    }
    __syncthreads();
    float rstd = rsqrtf(red2[0] * (1.f / CC) + 1e-5f);
    float4 wv = ((const float4*)w)[t];
    float4 bv = ((const float4*)b)[t];
    float4 o;
    o.x = dx * rstd * wv.x + bv.x;
    o.y = dy * rstd * wv.y + bv.y;
    o.z = dz * rstd * wv.z + bv.z;
    o.w = dw * rstd * wv.w + bv.w;
    ((float4*)(out + (size_t)row * CC))[t] = o;
}

// ---------------- Generic SGEMM 128x128x8, 256 threads, 8x8/thread ----------------
// Double-buffered smem pipeline: one __syncthreads per K-step, next tile's
// global loads issued before the FMA phase so their latency hides under compute.
// C[m,j] = sum_k A[m,k] * B(k,j),  B(k,j) = Bw[((j/hw)*K + k)*hw + (j%hw)]
// (hw = per-head output width; plain [K,N] weights use hw = N)
// Epilogue: + bias[j] (opt), ReLU (opt), + res[m,j] (opt).
// Requires: M%128==0, N%128==0, K%8==0, hw%4==0.
__global__ __launch_bounds__(256, 2)
void sgemm_kernel(const float* __restrict__ A, const float* __restrict__ Bw,
                  float* __restrict__ Cc, int M, int N, int K, int hw,
                  const float* __restrict__ bias, const float* __restrict__ res,
                  int relu)
{
    __shared__ float As[2][8][128];
    __shared__ float Bs[2][8][128];
    int tid = threadIdx.x;
    int bx = blockIdx.x, by = blockIdx.y;
    int ty = tid >> 4, tx = tid & 15;

    float acc[8][8];
#pragma unroll
    for (int i = 0; i < 8; i++)
#pragma unroll
        for (int j = 0; j < 8; j++) acc[i][j] = 0.f;

    // A tile load mapping: 128 rows x 8 cols, one float4 per thread
    int arow  = by * 128 + (tid >> 1);
    int acol4 = (tid & 1) * 4;
    const float* Ap = A + (size_t)arow * K + acol4;

    // B tile load mapping: 8 rows x 128 cols, one float4 per thread
    int bk = tid >> 5;
    int jl = (tid & 31) * 4;
    int j  = bx * 128 + jl;
    int head = j / hw;
    int jr   = j - head * hw;
    const float* Bp = Bw + (size_t)head * K * hw + (size_t)bk * hw + jr;

    int r = tid >> 1;

    // prologue: load tile 0 into buffer 0
    {
        float4 av = *(const float4*)(Ap);
        float4 bv = *(const float4*)(Bp);
        As[0][acol4 + 0][r] = av.x;
        As[0][acol4 + 1][r] = av.y;
        As[0][acol4 + 2][r] = av.z;
        As[0][acol4 + 3][r] = av.w;
        *(float4*)&Bs[0][bk][jl] = bv;
    }
    __syncthreads();

    int buf = 0;
    for (int k0 = 0; k0 < K; k0 += 8) {
        float4 av, bv;
        bool more = (k0 + 8 < K);
        if (more) {
            av = *(const float4*)(Ap + k0 + 8);
            bv = *(const float4*)(Bp + (size_t)(k0 + 8) * hw);
        }
#pragma unroll
        for (int kk = 0; kk < 8; kk++) {
            float a[8], bfr[8];
            *(float4*)(a)     = *(const float4*)&As[buf][kk][ty * 4];
            *(float4*)(a + 4) = *(const float4*)&As[buf][kk][64 + ty * 4];
            *(float4*)(bfr)     = *(const float4*)&Bs[buf][kk][tx * 4];
            *(float4*)(bfr + 4) = *(const float4*)&Bs[buf][kk][64 + tx * 4];
#pragma unroll
            for (int i = 0; i < 8; i++)
#pragma unroll
                for (int jj = 0; jj < 8; jj++)
                    acc[i][jj] += a[i] * bfr[jj];
        }
        if (more) {
            int nb = buf ^ 1;
            As[nb][acol4 + 0][r] = av.x;
            As[nb][acol4 + 1][r] = av.y;
            As[nb][acol4 + 2][r] = av.z;
            As[nb][acol4 + 3][r] = av.w;
            *(float4*)&Bs[nb][bk][jl] = bv;
            __syncthreads();
            buf = nb;
        }
    }

    // epilogue
#pragma unroll
    for (int ig = 0; ig < 2; ig++) {
#pragma unroll
        for (int rr = 0; rr < 4; rr++) {
            int row = by * 128 + ig * 64 + ty * 4 + rr;
            float* crow = Cc + (size_t)row * N;
            const float* rrow = res ? res + (size_t)row * N : nullptr;
#pragma unroll
            for (int jg = 0; jg < 2; jg++) {
                int col = bx * 128 + jg * 64 + tx * 4;
                float4 v;
                v.x = acc[ig * 4 + rr][jg * 4 + 0];
                v.y = acc[ig * 4 + rr][jg * 4 + 1];
                v.z = acc[ig * 4 + rr][jg * 4 + 2];
                v.w = acc[ig * 4 + rr][jg * 4 + 3];
                if (bias) {
                    float4 bb = *(const float4*)(bias + col);
                    v.x += bb.x; v.y += bb.y; v.z += bb.z; v.w += bb.w;
                }
                if (relu) {
                    v.x = fmaxf(v.x, 0.f); v.y = fmaxf(v.y, 0.f);
                    v.z = fmaxf(v.z, 0.f); v.w = fmaxf(v.w, 0.f);
                }
                if (rrow) {
                    float4 rr2 = *(const float4*)(rrow + col);
                    v.x += rr2.x; v.y += rr2.y; v.z += rr2.z; v.w += rr2.w;
                }
                *(float4*)(crow + col) = v;
            }
        }
    }
}

// ---------------- Fused attention (flash-style, 64x64 tiles) ----------------
// Per (b,h): q(t,d) = Qb[(b*T+t)*ldq + h*qh + d]
//            k(s,d) = Kb[(b*T+s)*ldk + h*kh + koff + d]
//            v(s,d) = Kb[(b*T+s)*ldk + h*kh + voff + d]
// Out written merged: Out[(b*T+t)*C + h*64 + d]
#define NEG_BIG (-1e30f)
__global__ __launch_bounds__(256)
void attn_kernel(const float* __restrict__ Qb, int ldq, int qh,
                 const float* __restrict__ Kb, int ldk, int kh, int koff, int voff,
                 float* __restrict__ Out, int causal)
{
    extern __shared__ float sm[];
    float* qs = sm;               // [64][64]
    float* ks = sm + 64 * 64;     // [64][65], aliased by P after S is computed
    float* vs = ks + 64 * 65;     // [64][64]

    int tid = threadIdx.x, ty = tid >> 4, tx = tid & 15;
    int qt = blockIdx.x;
    int bh = blockIdx.y;
    int b = bh >> 4, h = bh & 15;

    const float* Qp = Qb + (size_t)(b * TT) * ldq + h * qh;
    const float* Kp = Kb + (size_t)(b * TT) * ldk + h * kh + koff;
    const float* Vp = Kb + (size_t)(b * TT) * ldk + h * kh + voff;

    // load Q tile (64x64)
#pragma unroll
    for (int it = 0; it < 4; it++) {
        int f = tid + it * 256;           // float4 index, 0..1023
        int r = f >> 4, c4 = (f & 15) * 4;
        *(float4*)&qs[r * 64 + c4] =
            *(const float4*)(Qp + (size_t)(qt * 64 + r) * ldq + c4);
    }

    float m[4], l[4], o[4][4];
#pragma unroll
    for (int r = 0; r < 4; r++) {
        m[r] = NEG_BIG; l[r] = 0.f;
#pragma unroll
        for (int c = 0; c < 4; c++) o[r][c] = 0.f;
    }

    int ntiles = causal ? (qt + 1) : (TT / 64);
    for (int kt = 0; kt < ntiles; kt++) {
        __syncthreads();  // prior-iter reads of ks(P)/vs done; qs writes visible after
        // load K,V tiles
#pragma unroll
        for (int it = 0; it < 4; it++) {
            int f = tid + it * 256;
            int r = f >> 4, c4 = (f & 15) * 4;
            float4 kvv = *(const float4*)(Kp + (size_t)(kt * 64 + r) * ldk + c4);
            ks[r * 65 + c4 + 0] = kvv.x;
            ks[r * 65 + c4 + 1] = kvv.y;
            ks[r * 65 + c4 + 2] = kvv.z;
            ks[r * 65 + c4 + 3] = kvv.w;
            *(float4*)&vs[r * 64 + c4] =
                *(const float4*)(Vp + (size_t)(kt * 64 + r) * ldk + c4);
        }
        __syncthreads();

        // S = Q K^T (each thread 4x4)
        float s[4][4];
#pragma unroll
        for (int r = 0; r < 4; r++)
#pragma unroll
            for (int c = 0; c < 4; c++) s[r][c] = 0.f;
#pragma unroll 4
        for (int d = 0; d < 64; d++) {
            float qv[4], kv[4];
#pragma unroll
            for (int r = 0; r < 4; r++) qv[r] = qs[(ty * 4 + r) * 64 + d];
#pragma unroll
            for (int c = 0; c < 4; c++) kv[c] = ks[(tx * 4 + c) * 65 + d];
#pragma unroll
            for (int r = 0; r < 4; r++)
#pragma unroll
                for (int c = 0; c < 4; c++) s[r][c] += qv[r] * kv[c];
        }
        const float scale = 0.125f;  // D^-0.5
#pragma unroll
        for (int r = 0; r < 4; r++)
#pragma unroll
            for (int c = 0; c < 4; c++) s[r][c] *= scale;

        if (causal && kt == qt) {
#pragma unroll
            for (int r = 0; r < 4; r++)
#pragma unroll
                for (int c = 0; c < 4; c++)
                    if ((tx * 4 + c) > (ty * 4 + r)) s[r][c] = NEG_BIG;
        }

        // online softmax update (stats replicated across the 16 tx lanes)
        float alpha[4];
#pragma unroll
        for (int r = 0; r < 4; r++) {
            float tmax = fmaxf(fmaxf(s[r][0], s[r][1]), fmaxf(s[r][2], s[r][3]));
            for (int off = 8; off; off >>= 1)
                tmax = fmaxf(tmax, __shfl_xor_sync(0xffffffffu, tmax, off, 16));
            float newm = fmaxf(m[r], tmax);
            alpha[r] = __expf(m[r] - newm);
            m[r] = newm;
            float rs = 0.f;
#pragma unroll
            for (int c = 0; c < 4; c++) { s[r][c] = __expf(s[r][c] - newm); rs += s[r][c]; }
            for (int off = 8; off; off >>= 1)
                rs += __shfl_xor_sync(0xffffffffu, rs, off, 16);
            l[r] = l[r] * alpha[r] + rs;
#pragma unroll
            for (int c = 0; c < 4; c++) o[r][c] *= alpha[r];
        }

        __syncthreads();  // everyone done reading ks before it becomes P
        float* ps = ks;
#pragma unroll
        for (int r = 0; r < 4; r++)
#pragma unroll
            for (int c = 0; c < 4; c++)
                ps[(ty * 4 + r) * 65 + tx * 4 + c] = s[r][c];
        __syncthreads();

        // O += P @ V
#pragma unroll 4
        for (int jj = 0; jj < 64; jj++) {
            float pv[4];
#pragma unroll
            for (int r = 0; r < 4; r++) pv[r] = ps[(ty * 4 + r) * 65 + jj];
            float4 vv = *(const float4*)&vs[jj * 64 + tx * 4];
#pragma unroll
            for (int r = 0; r < 4; r++) {
                o[r][0] += pv[r] * vv.x;
                o[r][1] += pv[r] * vv.y;
                o[r][2] += pv[r] * vv.z;
                o[r][3] += pv[r] * vv.w;
            }
        }
    }

    // finalize + store merged
#pragma unroll
    for (int r = 0; r < 4; r++) {
        float inv = 1.f / l[r];
        float4 v;
        v.x = o[r][0] * inv; v.y = o[r][1] * inv;
        v.z = o[r][2] * inv; v.w = o[r][3] * inv;
        size_t row = (size_t)(b * TT + qt * 64 + ty * 4 + r);
        *(float4*)(Out + row * CC + h * 64 + tx * 4) = v;
    }
}

// ---------------- driver ----------------
extern "C" void kernel_launch(void* const* d_in, const int* in_sizes, int n_in,
                              void* d_out, int out_size)
{
    (void)in_sizes; (void)n_in; (void)out_size;
    const float* x      = (const float*)d_in[0];
    const float* enc    = (const float*)d_in[1];
    const float* w_qkv  = (const float*)d_in[2];
    const float* w_proj = (const float*)d_in[3];
    const float* b_proj = (const float*)d_in[4];
    const float* cw_q   = (const float*)d_in[5];
    const float* cw_kv  = (const float*)d_in[6];
    const float* cw_proj= (const float*)d_in[7];
    const float* cb_proj= (const float*)d_in[8];
    const float* ff1_w1 = (const float*)d_in[9];
    const float* ff1_b1 = (const float*)d_in[10];
    const float* ff1_w2 = (const float*)d_in[11];
    const float* ff1_b2 = (const float*)d_in[12];
    const float* ff2_w1 = (const float*)d_in[13];
    const float* ff2_b1 = (const float*)d_in[14];
    const float* ff2_w2 = (const float*)d_in[15];
    const float* ff2_b2 = (const float*)d_in[16];
    const float* ln1w = (const float*)d_in[17];
    const float* ln1b = (const float*)d_in[18];
    const float* ln2w = (const float*)d_in[19];
    const float* ln2b = (const float*)d_in[20];
    const float* ln3w = (const float*)d_in[21];
    const float* ln3b = (const float*)d_in[22];
    const float* ln4w = (const float*)d_in[23];
    const float* ln4b = (const float*)d_in[24];
    float* out = (float*)d_out;

    float *h, *qkv, *attn, *ff;
    cudaGetSymbolAddress((void**)&h,    g_h);
    cudaGetSymbolAddress((void**)&qkv,  g_qkv);
    cudaGetSymbolAddress((void**)&attn, g_attn);
    cudaGetSymbolAddress((void**)&ff,   g_ff);

    const int M = MR;
    const size_t asmem = (size_t)(64*64 + 64*65 + 64*64) * sizeof(float); // 49408
    cudaFuncSetAttribute(attn_kernel, cudaFuncAttributeMaxDynamicSharedMemorySize, (int)asmem);

    // ---- self-attention block ----
    ln_kernel<<<M, 256>>>(x, ln1w, ln1b, h);
    sgemm_kernel<<<dim3(3072/128, M/128), 256>>>(h, w_qkv, qkv, M, 3072, CC, 192,
                                                 nullptr, nullptr, 0);
    attn_kernel<<<dim3(TT/64, BB*HH), 256, asmem>>>(qkv, 3072, 192,
                                                    qkv, 3072, 192, 64, 128,
                                                    attn, 1);
    sgemm_kernel<<<dim3(CC/128, M/128), 256>>>(attn, w_proj, out, M, CC, CC, CC,
                                               b_proj, x, 0);

    // ---- feed-forward 1 ----
    ln_kernel<<<M, 256>>>(out, ln2w, ln2b, h);
    sgemm_kernel<<<dim3(FFD/128, M/128), 256>>>(h, ff1_w1, ff, M, FFD, CC, FFD,
                                                ff1_b1, nullptr, 1);
    sgemm_kernel<<<dim3(CC/128, M/128), 256>>>(ff, ff1_w2, out, M, CC, FFD, CC,
                                               ff1_b2, out, 0);

    // ---- cross-attention block ----
    ln_kernel<<<M, 256>>>(out, ln3w, ln3b, h);
    sgemm_kernel<<<dim3(CC/128, M/128), 256>>>(h, cw_q, qkv, M, CC, CC, 64,
                                               nullptr, nullptr, 0);
    float* kvbuf = qkv + (size_t)M * CC;
    sgemm_kernel<<<dim3(2048/128, M/128), 256>>>(enc, cw_kv, kvbuf, M, 2048, CC, 128,
                                                 nullptr, nullptr, 0);
    attn_kernel<<<dim3(TT/64, BB*HH), 256, asmem>>>(qkv, CC, 64,
                                                    kvbuf, 2048, 128, 0, 64,
                                                    attn, 0);
    sgemm_kernel<<<dim3(CC/128, M/128), 256>>>(attn, cw_proj, out, M, CC, CC, CC,
                                               cb_proj, out, 0);

    // ---- feed-forward 2 ----
    ln_kernel<<<M, 256>>>(out, ln4w, ln4b, h);
    sgemm_kernel<<<dim3(FFD/128, M/128), 256>>>(h, ff2_w1, ff, M, FFD, CC, FFD,
                                                ff2_b1, nullptr, 1);
    sgemm_kernel<<<dim3(CC/128, M/128), 256>>>(ff, ff2_w2, out, M, CC, FFD, CC,
                                               ff2_b2, out, 0);
}

// round 5
// speedup vs baseline: 2.0610x; 2.0610x over previous
#include <cuda_runtime.h>
#include <math.h>
#include <stdint.h>

// Problem constants
#define BB   4
#define TT   1024
#define CC   1024
#define HH   16
#define DD   64
#define FFD  4096
#define MR   (BB*TT)   // 4096 rows

// ---------------- scratch (allocation-free) ----------------
__device__ float g_h[(size_t)MR * CC];        // 16 MB  - LN output
__device__ float g_qkv[(size_t)MR * 3072];    // 48 MB  - qkv / (q + kv for cross)
__device__ float g_attn[(size_t)MR * CC];     // 16 MB  - merged attention out
__device__ float g_ff[(size_t)MR * FFD];      // 64 MB  - ff hidden

// ---------------- LayerNorm: one block per row, float4 I/O ----------------
__global__ __launch_bounds__(256)
void ln_kernel(const float* __restrict__ x, const float* __restrict__ w,
               const float* __restrict__ b, float* __restrict__ out)
{
    int row = blockIdx.x;
    int t = threadIdx.x;
    const float4* xr = (const float4*)(x + (size_t)row * CC);
    float4 v = xr[t];
    float s = v.x + v.y + v.z + v.w;
    __shared__ float red[8];
    __shared__ float red2[8];
    for (int off = 16; off; off >>= 1) s += __shfl_xor_sync(0xffffffffu, s, off);
    if ((t & 31) == 0) red[t >> 5] = s;
    __syncthreads();
    if (t < 8) {
        s = red[t];
        for (int off = 4; off; off >>= 1) s += __shfl_xor_sync(0xffu, s, off);
        if (t == 0) red[0] = s;
    }
    __syncthreads();
    float mu = red[0] * (1.f / CC);
    float dx = v.x - mu, dy = v.y - mu, dz = v.z - mu, dw = v.w - mu;
    float vv = dx*dx + dy*dy + dz*dz + dw*dw;
    for (int off = 16; off; off >>= 1) vv += __shfl_xor_sync(0xffffffffu, vv, off);
    if ((t & 31) == 0) red2[t >> 5] = vv;
    __syncthreads();
    if (t < 8) {
        vv = red2[t];
        for (int off = 4; off; off >>= 1) vv += __shfl_xor_sync(0xffu, vv, off);
        if (t == 0) red2[0] = vv;
    }
    __syncthreads();
    float rstd = rsqrtf(red2[0] * (1.f / CC) + 1e-5f);
    float4 wv = ((const float4*)w)[t];
    float4 bv = ((const float4*)b)[t];
    float4 o;
    o.x = dx * rstd * wv.x + bv.x;
    o.y = dy * rstd * wv.y + bv.y;
    o.z = dz * rstd * wv.z + bv.z;
    o.w = dw * rstd * wv.w + bv.w;
    ((float4*)(out + (size_t)row * CC))[t] = o;
}

// ---------------- TF32 tensor-core GEMM ----------------
// 128x128 block tile, BK=16, 256 threads = 8 warps (2x4), warp tile 64x32,
// m16n8k8 tf32 mma atoms (4x4 per warp). Double-buffered smem.
// B(k,j) = Bw[((j/hw)*K + k)*hw + (j%hw)]  (head-major weights; plain = hw==N)
// Epilogue: +bias, ReLU, +residual (all optional).
// Requires: M%128==0, N%128==0, K%16==0, hw%4==0.

__device__ __forceinline__ uint32_t f2tf32(float x) {
    uint32_t u;
    asm("cvt.rna.tf32.f32 %0, %1;" : "=r"(u) : "f"(x));
    return u;
}

__device__ __forceinline__ void mma_tf32(float* d, const uint32_t* a, const uint32_t* b) {
    asm volatile(
        "mma.sync.aligned.m16n8k8.row.col.f32.tf32.tf32.f32 "
        "{%0,%1,%2,%3}, {%4,%5,%6,%7}, {%8,%9}, {%0,%1,%2,%3};\n"
        : "+f"(d[0]), "+f"(d[1]), "+f"(d[2]), "+f"(d[3])
        : "r"(a[0]), "r"(a[1]), "r"(a[2]), "r"(a[3]),
          "r"(b[0]), "r"(b[1]));
}

#define AS_STRIDE 20    // 128 rows x 20 (pad 4): frag-load banks 20*grp+tig -> conflict-free
#define BS_STRIDE 136   // 16 rows x 136 (pad 8): frag-load banks 8*tig+grp -> conflict-free

__global__ __launch_bounds__(256, 2)
void tf32gemm_kernel(const float* __restrict__ A, const float* __restrict__ Bw,
                     float* __restrict__ Cc, int M, int N, int K, int hw,
                     const float* __restrict__ bias, const float* __restrict__ res,
                     int relu)
{
    __shared__ uint32_t As[2][128 * AS_STRIDE];
    __shared__ uint32_t Bs[2][16 * BS_STRIDE];

    int tid = threadIdx.x;
    int lane = tid & 31, wid = tid >> 5;
    int grp = lane >> 2, tig = lane & 3;
    int mw = (wid >> 2) * 64;     // warp M offset within block
    int nwp = (wid & 3) * 32;     // warp N offset within block
    int bx = blockIdx.x, by = blockIdx.y;

    float acc[4][4][4];
#pragma unroll
    for (int i = 0; i < 4; i++)
#pragma unroll
        for (int j = 0; j < 4; j++)
#pragma unroll
            for (int r = 0; r < 4; r++) acc[i][j][r] = 0.f;

    // A global load mapping: 128x16 tile, thread -> rows (tid>>2, +64), cols (tid&3)*4..+3
    int arow = tid >> 2;
    int acol = (tid & 3) * 4;
    const float* Ap0 = A + (size_t)(by * 128 + arow) * K + acol;
    const float* Ap1 = Ap0 + (size_t)64 * K;

    // B global load mapping: 16x128 tile, thread -> k rows (tid>>5, +8), cols lane*4..+3
    int brow = tid >> 5;
    int bn4 = lane * 4;
    int j = bx * 128 + bn4;
    int head = j / hw;
    int jr = j - head * hw;
    const float* Bp = Bw + (size_t)head * K * hw + jr;  // element (k, j) at Bp + k*hw

    // prologue: tile 0 -> buffer 0
    {
        float4 a0v = *(const float4*)(Ap0);
        float4 a1v = *(const float4*)(Ap1);
        float4 b0v = *(const float4*)(Bp + (size_t)brow * hw);
        float4 b1v = *(const float4*)(Bp + (size_t)(brow + 8) * hw);
        uint32_t* Asb = As[0];
        uint32_t* Bsb = Bs[0];
        Asb[arow * AS_STRIDE + acol + 0] = f2tf32(a0v.x);
        Asb[arow * AS_STRIDE + acol + 1] = f2tf32(a0v.y);
        Asb[arow * AS_STRIDE + acol + 2] = f2tf32(a0v.z);
        Asb[arow * AS_STRIDE + acol + 3] = f2tf32(a0v.w);
        Asb[(arow + 64) * AS_STRIDE + acol + 0] = f2tf32(a1v.x);
        Asb[(arow + 64) * AS_STRIDE + acol + 1] = f2tf32(a1v.y);
        Asb[(arow + 64) * AS_STRIDE + acol + 2] = f2tf32(a1v.z);
        Asb[(arow + 64) * AS_STRIDE + acol + 3] = f2tf32(a1v.w);
        Bsb[brow * BS_STRIDE + bn4 + 0] = f2tf32(b0v.x);
        Bsb[brow * BS_STRIDE + bn4 + 1] = f2tf32(b0v.y);
        Bsb[brow * BS_STRIDE + bn4 + 2] = f2tf32(b0v.z);
        Bsb[brow * BS_STRIDE + bn4 + 3] = f2tf32(b0v.w);
        Bsb[(brow + 8) * BS_STRIDE + bn4 + 0] = f2tf32(b1v.x);
        Bsb[(brow + 8) * BS_STRIDE + bn4 + 1] = f2tf32(b1v.y);
        Bsb[(brow + 8) * BS_STRIDE + bn4 + 2] = f2tf32(b1v.z);
        Bsb[(brow + 8) * BS_STRIDE + bn4 + 3] = f2tf32(b1v.w);
    }
    __syncthreads();

    int buf = 0;
    for (int k0 = 0; k0 < K; k0 += 16) {
        bool more = (k0 + 16 < K);
        float4 na0, na1, nb0, nb1;
        if (more) {
            na0 = *(const float4*)(Ap0 + k0 + 16);
            na1 = *(const float4*)(Ap1 + k0 + 16);
            nb0 = *(const float4*)(Bp + (size_t)(k0 + 16 + brow) * hw);
            nb1 = *(const float4*)(Bp + (size_t)(k0 + 24 + brow) * hw);
        }

        const uint32_t* Asb = As[buf];
        const uint32_t* Bsb = Bs[buf];
#pragma unroll
        for (int ks = 0; ks < 16; ks += 8) {
            uint32_t af[4][4], bf[4][2];
#pragma unroll
            for (int ma = 0; ma < 4; ma++) {
                int rb = mw + ma * 16 + grp;
                af[ma][0] = Asb[rb * AS_STRIDE + ks + tig];
                af[ma][1] = Asb[(rb + 8) * AS_STRIDE + ks + tig];
                af[ma][2] = Asb[rb * AS_STRIDE + ks + tig + 4];
                af[ma][3] = Asb[(rb + 8) * AS_STRIDE + ks + tig + 4];
            }
#pragma unroll
            for (int na = 0; na < 4; na++) {
                int cb = nwp + na * 8 + grp;
                bf[na][0] = Bsb[(ks + tig) * BS_STRIDE + cb];
                bf[na][1] = Bsb[(ks + tig + 4) * BS_STRIDE + cb];
            }
#pragma unroll
            for (int ma = 0; ma < 4; ma++)
#pragma unroll
                for (int na = 0; na < 4; na++)
                    mma_tf32(acc[ma][na], af[ma], bf[na]);
        }

        if (more) {
            int nb = buf ^ 1;
            uint32_t* Asn = As[nb];
            uint32_t* Bsn = Bs[nb];
            Asn[arow * AS_STRIDE + acol + 0] = f2tf32(na0.x);
            Asn[arow * AS_STRIDE + acol + 1] = f2tf32(na0.y);
            Asn[arow * AS_STRIDE + acol + 2] = f2tf32(na0.z);
            Asn[arow * AS_STRIDE + acol + 3] = f2tf32(na0.w);
            Asn[(arow + 64) * AS_STRIDE + acol + 0] = f2tf32(na1.x);
            Asn[(arow + 64) * AS_STRIDE + acol + 1] = f2tf32(na1.y);
            Asn[(arow + 64) * AS_STRIDE + acol + 2] = f2tf32(na1.z);
            Asn[(arow + 64) * AS_STRIDE + acol + 3] = f2tf32(na1.w);
            Bsn[brow * BS_STRIDE + bn4 + 0] = f2tf32(nb0.x);
            Bsn[brow * BS_STRIDE + bn4 + 1] = f2tf32(nb0.y);
            Bsn[brow * BS_STRIDE + bn4 + 2] = f2tf32(nb0.z);
            Bsn[brow * BS_STRIDE + bn4 + 3] = f2tf32(nb0.w);
            Bsn[(brow + 8) * BS_STRIDE + bn4 + 0] = f2tf32(nb1.x);
            Bsn[(brow + 8) * BS_STRIDE + bn4 + 1] = f2tf32(nb1.y);
            Bsn[(brow + 8) * BS_STRIDE + bn4 + 2] = f2tf32(nb1.z);
            Bsn[(brow + 8) * BS_STRIDE + bn4 + 3] = f2tf32(nb1.w);
            __syncthreads();
            buf = nb;
        }
    }

    // epilogue: acc[ma][na] regs map to (row0,col),(row0,col+1),(row0+8,col),(row0+8,col+1)
#pragma unroll
    for (int ma = 0; ma < 4; ma++) {
        int row0 = by * 128 + mw + ma * 16 + grp;
        int row1 = row0 + 8;
#pragma unroll
        for (int na = 0; na < 4; na++) {
            int col = bx * 128 + nwp + na * 8 + 2 * tig;
            float v0 = acc[ma][na][0], v1 = acc[ma][na][1];
            float v2 = acc[ma][na][2], v3 = acc[ma][na][3];
            if (bias) {
                float b0 = bias[col], b1 = bias[col + 1];
                v0 += b0; v1 += b1; v2 += b0; v3 += b1;
            }
            if (relu) {
                v0 = fmaxf(v0, 0.f); v1 = fmaxf(v1, 0.f);
                v2 = fmaxf(v2, 0.f); v3 = fmaxf(v3, 0.f);
            }
            if (res) {
                float2 r0 = *(const float2*)(res + (size_t)row0 * N + col);
                float2 r1 = *(const float2*)(res + (size_t)row1 * N + col);
                v0 += r0.x; v1 += r0.y; v2 += r1.x; v3 += r1.y;
            }
            float2 o0 = make_float2(v0, v1);
            float2 o1 = make_float2(v2, v3);
            *(float2*)(Cc + (size_t)row0 * N + col) = o0;
            *(float2*)(Cc + (size_t)row1 * N + col) = o1;
        }
    }
}

// ---------------- Fused attention (flash-style, 64x64 tiles) ----------------
#define NEG_BIG (-1e30f)
__global__ __launch_bounds__(256)
void attn_kernel(const float* __restrict__ Qb, int ldq, int qh,
                 const float* __restrict__ Kb, int ldk, int kh, int koff, int voff,
                 float* __restrict__ Out, int causal)
{
    extern __shared__ float sm[];
    float* qs = sm;               // [64][64]
    float* ks = sm + 64 * 64;     // [64][65], aliased by P after S is computed
    float* vs = ks + 64 * 65;     // [64][64]

    int tid = threadIdx.x, ty = tid >> 4, tx = tid & 15;
    int qt = blockIdx.x;
    int bh = blockIdx.y;
    int b = bh >> 4, h = bh & 15;

    const float* Qp = Qb + (size_t)(b * TT) * ldq + h * qh;
    const float* Kp = Kb + (size_t)(b * TT) * ldk + h * kh + koff;
    const float* Vp = Kb + (size_t)(b * TT) * ldk + h * kh + voff;

#pragma unroll
    for (int it = 0; it < 4; it++) {
        int f = tid + it * 256;
        int r = f >> 4, c4 = (f & 15) * 4;
        *(float4*)&qs[r * 64 + c4] =
            *(const float4*)(Qp + (size_t)(qt * 64 + r) * ldq + c4);
    }

    float m[4], l[4], o[4][4];
#pragma unroll
    for (int r = 0; r < 4; r++) {
        m[r] = NEG_BIG; l[r] = 0.f;
#pragma unroll
        for (int c = 0; c < 4; c++) o[r][c] = 0.f;
    }

    int ntiles = causal ? (qt + 1) : (TT / 64);
    for (int kt = 0; kt < ntiles; kt++) {
        __syncthreads();
#pragma unroll
        for (int it = 0; it < 4; it++) {
            int f = tid + it * 256;
            int r = f >> 4, c4 = (f & 15) * 4;
            float4 kvv = *(const float4*)(Kp + (size_t)(kt * 64 + r) * ldk + c4);
            ks[r * 65 + c4 + 0] = kvv.x;
            ks[r * 65 + c4 + 1] = kvv.y;
            ks[r * 65 + c4 + 2] = kvv.z;
            ks[r * 65 + c4 + 3] = kvv.w;
            *(float4*)&vs[r * 64 + c4] =
                *(const float4*)(Vp + (size_t)(kt * 64 + r) * ldk + c4);
        }
        __syncthreads();

        float s[4][4];
#pragma unroll
        for (int r = 0; r < 4; r++)
#pragma unroll
            for (int c = 0; c < 4; c++) s[r][c] = 0.f;
#pragma unroll 4
        for (int d = 0; d < 64; d++) {
            float qv[4], kv[4];
#pragma unroll
            for (int r = 0; r < 4; r++) qv[r] = qs[(ty * 4 + r) * 64 + d];
#pragma unroll
            for (int c = 0; c < 4; c++) kv[c] = ks[(tx * 4 + c) * 65 + d];
#pragma unroll
            for (int r = 0; r < 4; r++)
#pragma unroll
                for (int c = 0; c < 4; c++) s[r][c] += qv[r] * kv[c];
        }
        const float scale = 0.125f;
#pragma unroll
        for (int r = 0; r < 4; r++)
#pragma unroll
            for (int c = 0; c < 4; c++) s[r][c] *= scale;

        if (causal && kt == qt) {
#pragma unroll
            for (int r = 0; r < 4; r++)
#pragma unroll
                for (int c = 0; c < 4; c++)
                    if ((tx * 4 + c) > (ty * 4 + r)) s[r][c] = NEG_BIG;
        }

        float alpha[4];
#pragma unroll
        for (int r = 0; r < 4; r++) {
            float tmax = fmaxf(fmaxf(s[r][0], s[r][1]), fmaxf(s[r][2], s[r][3]));
            for (int off = 8; off; off >>= 1)
                tmax = fmaxf(tmax, __shfl_xor_sync(0xffffffffu, tmax, off, 16));
            float newm = fmaxf(m[r], tmax);
            alpha[r] = __expf(m[r] - newm);
            m[r] = newm;
            float rs = 0.f;
#pragma unroll
            for (int c = 0; c < 4; c++) { s[r][c] = __expf(s[r][c] - newm); rs += s[r][c]; }
            for (int off = 8; off; off >>= 1)
                rs += __shfl_xor_sync(0xffffffffu, rs, off, 16);
            l[r] = l[r] * alpha[r] + rs;
#pragma unroll
            for (int c = 0; c < 4; c++) o[r][c] *= alpha[r];
        }

        __syncthreads();
        float* ps = ks;
#pragma unroll
        for (int r = 0; r < 4; r++)
#pragma unroll
            for (int c = 0; c < 4; c++)
                ps[(ty * 4 + r) * 65 + tx * 4 + c] = s[r][c];
        __syncthreads();

#pragma unroll 4
        for (int jj = 0; jj < 64; jj++) {
            float pv[4];
#pragma unroll
            for (int r = 0; r < 4; r++) pv[r] = ps[(ty * 4 + r) * 65 + jj];
            float4 vv = *(const float4*)&vs[jj * 64 + tx * 4];
#pragma unroll
            for (int r = 0; r < 4; r++) {
                o[r][0] += pv[r] * vv.x;
                o[r][1] += pv[r] * vv.y;
                o[r][2] += pv[r] * vv.z;
                o[r][3] += pv[r] * vv.w;
            }
        }
    }

#pragma unroll
    for (int r = 0; r < 4; r++) {
        float inv = 1.f / l[r];
        float4 v;
        v.x = o[r][0] * inv; v.y = o[r][1] * inv;
        v.z = o[r][2] * inv; v.w = o[r][3] * inv;
        size_t row = (size_t)(b * TT + qt * 64 + ty * 4 + r);
        *(float4*)(Out + row * CC + h * 64 + tx * 4) = v;
    }
}

// ---------------- driver ----------------
extern "C" void kernel_launch(void* const* d_in, const int* in_sizes, int n_in,
                              void* d_out, int out_size)
{
    (void)in_sizes; (void)n_in; (void)out_size;
    const float* x      = (const float*)d_in[0];
    const float* enc    = (const float*)d_in[1];
    const float* w_qkv  = (const float*)d_in[2];
    const float* w_proj = (const float*)d_in[3];
    const float* b_proj = (const float*)d_in[4];
    const float* cw_q   = (const float*)d_in[5];
    const float* cw_kv  = (const float*)d_in[6];
    const float* cw_proj= (const float*)d_in[7];
    const float* cb_proj= (const float*)d_in[8];
    const float* ff1_w1 = (const float*)d_in[9];
    const float* ff1_b1 = (const float*)d_in[10];
    const float* ff1_w2 = (const float*)d_in[11];
    const float* ff1_b2 = (const float*)d_in[12];
    const float* ff2_w1 = (const float*)d_in[13];
    const float* ff2_b1 = (const float*)d_in[14];
    const float* ff2_w2 = (const float*)d_in[15];
    const float* ff2_b2 = (const float*)d_in[16];
    const float* ln1w = (const float*)d_in[17];
    const float* ln1b = (const float*)d_in[18];
    const float* ln2w = (const float*)d_in[19];
    const float* ln2b = (const float*)d_in[20];
    const float* ln3w = (const float*)d_in[21];
    const float* ln3b = (const float*)d_in[22];
    const float* ln4w = (const float*)d_in[23];
    const float* ln4b = (const float*)d_in[24];
    float* out = (float*)d_out;

    float *h, *qkv, *attn, *ff;
    cudaGetSymbolAddress((void**)&h,    g_h);
    cudaGetSymbolAddress((void**)&qkv,  g_qkv);
    cudaGetSymbolAddress((void**)&attn, g_attn);
    cudaGetSymbolAddress((void**)&ff,   g_ff);

    const int M = MR;
    const size_t asmem = (size_t)(64*64 + 64*65 + 64*64) * sizeof(float); // 49408
    cudaFuncSetAttribute(attn_kernel, cudaFuncAttributeMaxDynamicSharedMemorySize, (int)asmem);

    // ---- self-attention block ----
    ln_kernel<<<M, 256>>>(x, ln1w, ln1b, h);
    tf32gemm_kernel<<<dim3(3072/128, M/128), 256>>>(h, w_qkv, qkv, M, 3072, CC, 192,
                                                    nullptr, nullptr, 0);
    attn_kernel<<<dim3(TT/64, BB*HH), 256, asmem>>>(qkv, 3072, 192,
                                                    qkv, 3072, 192, 64, 128,
                                                    attn, 1);
    tf32gemm_kernel<<<dim3(CC/128, M/128), 256>>>(attn, w_proj, out, M, CC, CC, CC,
                                                  b_proj, x, 0);

    // ---- feed-forward 1 ----
    ln_kernel<<<M, 256>>>(out, ln2w, ln2b, h);
    tf32gemm_kernel<<<dim3(FFD/128, M/128), 256>>>(h, ff1_w1, ff, M, FFD, CC, FFD,
                                                   ff1_b1, nullptr, 1);
    tf32gemm_kernel<<<dim3(CC/128, M/128), 256>>>(ff, ff1_w2, out, M, CC, FFD, CC,
                                                  ff1_b2, out, 0);

    // ---- cross-attention block ----
    ln_kernel<<<M, 256>>>(out, ln3w, ln3b, h);
    tf32gemm_kernel<<<dim3(CC/128, M/128), 256>>>(h, cw_q, qkv, M, CC, CC, 64,
                                                  nullptr, nullptr, 0);
    float* kvbuf = qkv + (size_t)M * CC;
    tf32gemm_kernel<<<dim3(2048/128, M/128), 256>>>(enc, cw_kv, kvbuf, M, 2048, CC, 128,
                                                    nullptr, nullptr, 0);
    attn_kernel<<<dim3(TT/64, BB*HH), 256, asmem>>>(qkv, CC, 64,
                                                    kvbuf, 2048, 128, 0, 64,
                                                    attn, 0);
    tf32gemm_kernel<<<dim3(CC/128, M/128), 256>>>(attn, cw_proj, out, M, CC, CC, CC,
                                                  cb_proj, out, 0);

    // ---- feed-forward 2 ----
    ln_kernel<<<M, 256>>>(out, ln4w, ln4b, h);
    tf32gemm_kernel<<<dim3(FFD/128, M/128), 256>>>(h, ff2_w1, ff, M, FFD, CC, FFD,
                                                   ff2_b1, nullptr, 1);
    tf32gemm_kernel<<<dim3(CC/128, M/128), 256>>>(ff, ff2_w2, out, M, CC, FFD, CC,
                                                  ff2_b2, out, 0);
}